// round 3
// baseline (speedup 1.0000x reference)
#include <cuda_runtime.h>
#include <cuda_bf16.h>

// DrugBAN fused kernel, R2: finer grid for full occupancy.
//
// Algebraic simplification (verified R1, rel_err 2e-7): softmax rows sum to 1, so
//   drug_ctx[b,:] = (1/NT) * sum_{nodes i in graph b, rank<NMAX} drug_x[i,:]
//   tgt_ctx[b,:]  = (1/NT) * sum_t target_h[b,t,:]
// W_a and the attention GEMM/softmax cancel out entirely.
//
// R2 change: grid (64, 32) = 2048 blocks; each block owns a 16-dim slice
// (4 float4 columns) of either the drug segment-sum (parts 0..15) or the
// target mean (parts 16..31). 2048/148 SMs ~= 13.8 blocks/SM -> warp
// occupancy saturates (R1 was grid=512 -> 40% occ, the measured limiter).
//
// Inputs (metadata order):
//   d_in[0] drug_x    float32 [16384, 256]
//   d_in[1] batch_idx int32   [16384]   (sorted)
//   d_in[2] target_h  float32 [64, 1024, 256]
//   d_in[3] W_a       float32 [256, 256]  (mathematically unused)
// Output: float32 [64, 512]  (drug_ctx | tgt_ctx)

#define NT_LEN   1024
#define NMAX_CAP 512
#define BATCH_B  64

__device__ __forceinline__ int lb_search(const int* __restrict__ a, int n, int key) {
    int lo = 0, hi = n;
    while (lo < hi) {
        int mid = (lo + hi) >> 1;
        if (__ldg(a + mid) < key) lo = mid + 1; else hi = mid;
    }
    return lo;
}

__global__ __launch_bounds__(256, 8)
void drugban_fused_kernel(const float* __restrict__ drug_x,
                          const int*   __restrict__ batch_idx,
                          const float* __restrict__ target_h,
                          float*       __restrict__ out,
                          int n_nodes) {
    const int b    = blockIdx.x;     // batch 0..63
    const int part = blockIdx.y;     // 0..15 drug slices, 16..31 target slices
    const int tid  = threadIdx.x;    // 256 threads
    const int col  = tid & 3;        // float4 column within the 16-dim slice
    const int rg   = tid >> 2;       // 0..63 row group

    float4 acc = make_float4(0.f, 0.f, 0.f, 0.f);

    if (part < 16) {
        // ---- drug segment sum, dims [part*16, part*16+16) ----
        int start = lb_search(batch_idx, n_nodes, b);
        int end   = lb_search(batch_idx, n_nodes, b + 1);
        if (end - start > NMAX_CAP) end = start + NMAX_CAP;  // pos>=NMAX dropped

        // row stride: 256 floats = 64 float4
        const float4* base = reinterpret_cast<const float4*>(drug_x)
                             + (size_t)part * 4 + col;
        for (int i = start + rg; i < end; i += 64) {
            float4 v = base[(size_t)i * 64];
            acc.x += v.x; acc.y += v.y; acc.z += v.z; acc.w += v.w;
        }
    } else {
        // ---- target mean, dims [(part-16)*16, +16) ----
        const int q = part - 16;
        const float4* base = reinterpret_cast<const float4*>(target_h)
                             + (size_t)b * (NT_LEN * 64) + (size_t)q * 4 + col;
        // 1024 rows / 64 row-groups = 16 iterations; unroll for MLP
        #pragma unroll 4
        for (int t = rg; t < NT_LEN; t += 64) {
            float4 v = base[(size_t)t * 64];
            acc.x += v.x; acc.y += v.y; acc.z += v.z; acc.w += v.w;
        }
    }

    // ---- tree-reduce the 64 row groups (stride-4 layout keeps col fixed) ----
    __shared__ float4 red[256];
    red[tid] = acc;
    __syncthreads();
    #pragma unroll
    for (int s = 128; s >= 4; s >>= 1) {
        if (tid < s) {
            float4 o = red[tid + s];
            float4 m = red[tid];
            m.x += o.x; m.y += o.y; m.z += o.z; m.w += o.w;
            red[tid] = m;
        }
        __syncthreads();
    }

    if (tid < 4) {
        const float scale = 1.0f / (float)NT_LEN;  // both halves divide by NT
        float4 r = red[tid];
        r.x *= scale; r.y *= scale; r.z *= scale; r.w *= scale;
        // out layout: [b, 512] = [drug_ctx(256) | tgt_ctx(256)]
        int off = b * 512 + ((part < 16) ? part * 16 : 256 + (part - 16) * 16);
        reinterpret_cast<float4*>(out + off)[tid] = r;
    }
}

extern "C" void kernel_launch(void* const* d_in, const int* in_sizes, int n_in,
                              void* d_out, int out_size) {
    const float* drug_x    = (const float*)d_in[0];
    const int*   batch_idx = (const int*)d_in[1];
    const float* target_h  = (const float*)d_in[2];
    // d_in[3] (W_a) cancels out mathematically; unused.
    float* out = (float*)d_out;
    int n_nodes = in_sizes[1];

    dim3 grid(BATCH_B, 32);
    drugban_fused_kernel<<<grid, 256>>>(drug_x, batch_idx, target_h, out, n_nodes);
}

// round 4
// speedup vs baseline: 1.4254x; 1.4254x over previous
#include <cuda_runtime.h>
#include <cuda_bf16.h>

// DrugBAN fused kernel, R3: R1 access shape + balanced blocks via t-split.
//
// Algebra (verified R1/R2, rel_err ~2e-7): softmax rows sum to 1, so
//   drug_ctx[b,:] = (1/NT) * segment_sum(drug_x)  (rank < NMAX only)
//   tgt_ctx[b,:]  = mean_t target_h[b,t,:]
// W_a / GEMM / softmax cancel.
//
// R2 post-mortem: 16-dim column slices regressed (overhead up, coalescing
// down). R3 keeps R1's 64-dim slices but splits the 4x-heavier target blocks
// along t into 3 chunks -> 1024 uniform blocks, single wave, ~86% occ.
// Cross-block combine: deterministic last-block-reduces with fixed order.
//
// Inputs: d_in[0] drug_x f32[16384,256], d_in[1] batch_idx i32[16384] sorted,
//         d_in[2] target_h f32[64,1024,256], d_in[3] W_a (unused).
// Output: f32 [64, 512] = [drug_ctx | tgt_ctx].

#define NT_LEN   1024
#define NMAX_CAP 512
#define BATCH_B  64
#define TCHUNKS  3

// Scratch for target partials: [b][q][c][64] floats, and tickets per (b,q).
__device__ float g_partial[BATCH_B * 4 * TCHUNKS * 64];
__device__ int   g_ticket[BATCH_B * 4];   // zero-initialized; self-resetting

__device__ __forceinline__ int lb_search(const int* __restrict__ a, int n, int key) {
    int lo = 0, hi = n;
    while (lo < hi) {
        int mid = (lo + hi) >> 1;
        if (__ldg(a + mid) < key) lo = mid + 1; else hi = mid;
    }
    return lo;
}

__device__ __forceinline__ void block_reduce_16(float4* red, int tid) {
    // reduce 256 entries (16 cols x 16 rowgroups, stride-16) down to 16 cols
    __syncthreads();
    #pragma unroll
    for (int s = 128; s >= 16; s >>= 1) {
        if (tid < s) {
            float4 o = red[tid + s];
            float4 m = red[tid];
            m.x += o.x; m.y += o.y; m.z += o.z; m.w += o.w;
            red[tid] = m;
        }
        __syncthreads();
    }
}

__global__ __launch_bounds__(256, 8)
void drugban_fused_kernel(const float* __restrict__ drug_x,
                          const int*   __restrict__ batch_idx,
                          const float* __restrict__ target_h,
                          float*       __restrict__ out,
                          int n_nodes) {
    const int b    = blockIdx.x;     // batch 0..63
    const int part = blockIdx.y;     // 0..3 drug quarters, 4..15 target (q,c)
    const int tid  = threadIdx.x;    // 256 threads
    const int col  = tid & 15;       // float4 column within the 64-dim slice
    const int rg   = tid >> 4;       // 0..15 row group

    __shared__ float4 red[256];
    __shared__ int s_ticket;

    const float scale = 1.0f / (float)NT_LEN;
    float4 acc = make_float4(0.f, 0.f, 0.f, 0.f);

    if (part < 4) {
        // ---- drug segment sum, dims [part*64, +64) ----
        int start = lb_search(batch_idx, n_nodes, b);
        int end   = lb_search(batch_idx, n_nodes, b + 1);
        if (end - start > NMAX_CAP) end = start + NMAX_CAP;

        const float4* base = reinterpret_cast<const float4*>(drug_x)
                             + (size_t)part * 16 + col;   // row = 64 float4
        int i = start + rg;
        for (; i + 16 < end; i += 32) {
            float4 v0 = base[(size_t)i * 64];
            float4 v1 = base[(size_t)(i + 16) * 64];
            acc.x += v0.x + v1.x; acc.y += v0.y + v1.y;
            acc.z += v0.z + v1.z; acc.w += v0.w + v1.w;
        }
        if (i < end) {
            float4 v = base[(size_t)i * 64];
            acc.x += v.x; acc.y += v.y; acc.z += v.z; acc.w += v.w;
        }

        red[tid] = acc;
        block_reduce_16(red, tid);

        if (tid < 16) {
            float4 r = red[tid];
            r.x *= scale; r.y *= scale; r.z *= scale; r.w *= scale;
            reinterpret_cast<float4*>(out + b * 512 + part * 64)[tid] = r;
        }
    } else {
        // ---- target partial sum: quarter q, t-chunk c ----
        const int idx = part - 4;
        const int q = idx & 3;        // 64-dim slice 0..3
        const int c = idx >> 2;       // t-chunk 0..2
        const int t0 = (c * NT_LEN) / TCHUNKS;
        const int t1 = ((c + 1) * NT_LEN) / TCHUNKS;

        const float4* base = reinterpret_cast<const float4*>(target_h)
                             + (size_t)b * (NT_LEN * 64) + (size_t)q * 16 + col;
        #pragma unroll 4
        for (int t = t0 + rg; t < t1; t += 16) {
            float4 v = base[(size_t)t * 64];
            acc.x += v.x; acc.y += v.y; acc.z += v.z; acc.w += v.w;
        }

        red[tid] = acc;
        block_reduce_16(red, tid);

        // write partial (unscaled) to scratch
        float4* pslot = reinterpret_cast<float4*>(
            g_partial + (((b * 4 + q) * TCHUNKS + c) * 64));
        if (tid < 16) pslot[tid] = red[tid];

        // release partial, take ticket
        __threadfence();
        __syncthreads();
        if (tid == 0) s_ticket = atomicAdd(&g_ticket[b * 4 + q], 1);
        __syncthreads();

        if (s_ticket == TCHUNKS - 1) {
            __threadfence();  // acquire: make peers' partials visible
            if (tid < 16) {
                const float4* pbase = reinterpret_cast<const float4*>(
                    g_partial + ((b * 4 + q) * TCHUNKS * 64));
                // fixed summation order c = 0,1,2 -> deterministic
                float4 r = pbase[tid];
                float4 p1 = pbase[16 + tid];
                float4 p2 = pbase[32 + tid];
                r.x = (r.x + p1.x + p2.x) * scale;
                r.y = (r.y + p1.y + p2.y) * scale;
                r.z = (r.z + p1.z + p2.z) * scale;
                r.w = (r.w + p1.w + p2.w) * scale;
                reinterpret_cast<float4*>(out + b * 512 + 256 + q * 64)[tid] = r;
            }
            if (tid == 0) g_ticket[b * 4 + q] = 0;  // self-reset for next replay
        }
    }
}

extern "C" void kernel_launch(void* const* d_in, const int* in_sizes, int n_in,
                              void* d_out, int out_size) {
    const float* drug_x    = (const float*)d_in[0];
    const int*   batch_idx = (const int*)d_in[1];
    const float* target_h  = (const float*)d_in[2];
    // d_in[3] (W_a) cancels out mathematically; unused.
    float* out = (float*)d_out;
    int n_nodes = in_sizes[1];

    dim3 grid(BATCH_B, 4 + 4 * TCHUNKS);   // 64 x 16 = 1024 uniform blocks
    drugban_fused_kernel<<<grid, 256>>>(drug_x, batch_idx, target_h, out, n_nodes);
}